// round 4
// baseline (speedup 1.0000x reference)
#include <cuda_runtime.h>
#include <math.h>

#define BB 16
#define CC 512
#define NN 4096
#define KK 64
#define KC 16
#define NSPLIT 8
#define EPSF 1e-6f

typedef unsigned long long u64;

// Scratch (allocation-free per harness rules)
__device__ float g_b[BB * CC * KK];                    // current bases [bi][c][k]
__device__ float g_bnew[BB * CC * KK];                 // reduced bases pre-l2
__device__ float g_bsplit[NSPLIT * BB * CC * KK];      // per-split GEMM2 partials (16MB)
__device__ float g_colsum[BB * KK];                    // l1-norm denominators
__device__ float g_attn[(size_t)BB * NN * KK];         // attention [bi][n][k] (64MB)

// ---------------- f32x2 helpers (FFMA2 path) ----------------
__device__ __forceinline__ u64 pk2(float lo, float hi) {
    u64 r; asm("mov.b64 %0, {%1,%2};" : "=l"(r) : "f"(lo), "f"(hi)); return r;
}
__device__ __forceinline__ u64 dup2(float v) { return pk2(v, v); }
__device__ __forceinline__ void fma2(u64& d, u64 a, u64 b) {
    asm("fma.rn.f32x2 %0, %1, %2, %3;" : "=l"(d) : "l"(a), "l"(b), "l"(d));
}
__device__ __forceinline__ float2 up2(u64 v) {
    float2 r; asm("mov.b64 {%0,%1}, %2;" : "=f"(r.x), "=f"(r.y) : "l"(v)); return r;
}

// ---------------------------------------------------------------------------
// Normalize input bases (l2 over C) and broadcast to all batches.
__global__ void k_bases(const float* __restrict__ bases) {
    int k = blockIdx.x, t = threadIdx.x;
    __shared__ float red[128];
    float ss = 0.f;
    for (int c = t; c < CC; c += 128) { float v = bases[c * KK + k]; ss += v * v; }
    red[t] = ss; __syncthreads();
    for (int s = 64; s > 0; s >>= 1) { if (t < s) red[t] += red[t + s]; __syncthreads(); }
    float inv = 1.f / (EPSF + sqrtf(red[0]));
    for (int c = t; c < CC; c += 128) {
        float v = bases[c * KK + k] * inv;
        for (int bi = 0; bi < BB; bi++) g_b[(bi * CC + c) * KK + k] = v;
    }
}

__global__ void k_zero_cs() {
    int i = threadIdx.x;
    if (i < BB * KK) g_colsum[i] = 0.f;
}

// ---------------------------------------------------------------------------
// GEMM1: attn[n,k] = softmax_k( sum_c f[c,n]*b[c,k] ), plus column sums over n.
// 128 threads, tile 128n x 64k, micro 8x8 with split k-octet (tx*4 | tx*4+32).
__global__ void __launch_bounds__(128) k_gemm1(const float* __restrict__ f) {
    int bi = blockIdx.y, n0 = blockIdx.x * 128;
    int tid = threadIdx.x, tx = tid & 7, ty = tid >> 3;      // ty: 0..15 (n octet)
    __shared__ float As[KC][132];   // [cc][n]
    __shared__ float Bs[KC][68];    // [cc][k]
    __shared__ float s_cs[KK];
    const float* fb = f + (size_t)bi * CC * NN + n0;
    const float* bb = g_b + bi * CC * KK;

    u64 acc2[8][4];
#pragma unroll
    for (int i = 0; i < 8; i++)
#pragma unroll
        for (int j = 0; j < 4; j++) acc2[i][j] = 0ull;

    for (int c0 = 0; c0 < CC; c0 += KC) {
#pragma unroll
        for (int l = 0; l < 4; l++) {                 // As: 16x128 = 512 float4
            int idx = tid + l * 128;
            int r = idx >> 5, c4 = idx & 31;
            *(float4*)&As[r][c4 * 4] = *(const float4*)&fb[(size_t)(c0 + r) * NN + c4 * 4];
        }
#pragma unroll
        for (int l = 0; l < 2; l++) {                 // Bs: 16x64 = 256 float4
            int idx = tid + l * 128;
            int r = idx >> 4, c4 = idx & 15;
            *(float4*)&Bs[r][c4 * 4] = *(const float4*)&bb[(c0 + r) * KK + c4 * 4];
        }
        __syncthreads();
#pragma unroll
        for (int cc = 0; cc < KC; cc++) {
            float4 a0 = *(float4*)&As[cc][ty * 8];
            float4 a1 = *(float4*)&As[cc][ty * 8 + 4];
            float4 b0 = *(float4*)&Bs[cc][tx * 4];
            float4 b1 = *(float4*)&Bs[cc][tx * 4 + 32];
            u64 bp[4] = { pk2(b0.x, b0.y), pk2(b0.z, b0.w), pk2(b1.x, b1.y), pk2(b1.z, b1.w) };
            float av[8] = { a0.x, a0.y, a0.z, a0.w, a1.x, a1.y, a1.z, a1.w };
#pragma unroll
            for (int i = 0; i < 8; i++) {
                u64 ad = dup2(av[i]);
                fma2(acc2[i][0], ad, bp[0]);
                fma2(acc2[i][1], ad, bp[1]);
                fma2(acc2[i][2], ad, bp[2]);
                fma2(acc2[i][3], ad, bp[3]);
            }
        }
        __syncthreads();
    }

    if (tid < KK) s_cs[tid] = 0.f;
    __syncthreads();

    // Row softmax over k. Thread holds k = {tx*4..+3} U {32+tx*4..+3}; 8 tx lanes = full row.
    float* ap = g_attn + ((size_t)bi * NN + n0) * KK;
    float cssum[8];
#pragma unroll
    for (int j = 0; j < 8; j++) cssum[j] = 0.f;
#pragma unroll
    for (int i = 0; i < 8; i++) {
        float2 e0 = up2(acc2[i][0]), e1 = up2(acc2[i][1]);
        float2 e2 = up2(acc2[i][2]), e3 = up2(acc2[i][3]);
        float v[8] = { e0.x, e0.y, e1.x, e1.y, e2.x, e2.y, e3.x, e3.y };
        float m = v[0];
#pragma unroll
        for (int j = 1; j < 8; j++) m = fmaxf(m, v[j]);
#pragma unroll
        for (int o = 4; o > 0; o >>= 1) m = fmaxf(m, __shfl_xor_sync(0xffffffffu, m, o, 8));
        float s = 0.f;
#pragma unroll
        for (int j = 0; j < 8; j++) { float e = __expf(v[j] - m); v[j] = e; s += e; }
#pragma unroll
        for (int o = 4; o > 0; o >>= 1) s += __shfl_xor_sync(0xffffffffu, s, o, 8);
        float inv = 1.f / s;
#pragma unroll
        for (int j = 0; j < 8; j++) { v[j] *= inv; cssum[j] += v[j]; }
        float* row = ap + (size_t)(ty * 8 + i) * KK;
        *(float4*)(row + tx * 4)      = make_float4(v[0], v[1], v[2], v[3]);
        *(float4*)(row + 32 + tx * 4) = make_float4(v[4], v[5], v[6], v[7]);
    }
#pragma unroll
    for (int j = 0; j < 4; j++) atomicAdd(&s_cs[tx * 4 + j], cssum[j]);
#pragma unroll
    for (int j = 0; j < 4; j++) atomicAdd(&s_cs[32 + tx * 4 + j], cssum[4 + j]);
    __syncthreads();
    if (tid < KK) atomicAdd(&g_colsum[bi * KK + tid], s_cs[tid]);
}

// ---------------------------------------------------------------------------
// GEMM2: bsplit[s][c,k] = sum_{n in split s} f[c,n]*attn[n,k] / (eps+colsum[k])
// 128 threads, tile 128c x 64k, reduction over 512 n per block.
__global__ void __launch_bounds__(128) k_gemm2(const float* __restrict__ f) {
    int bi = blockIdx.z, c0 = blockIdx.y * 128, nbeg = blockIdx.x * (NN / NSPLIT);
    int tid = threadIdx.x, tx = tid & 7, ty = tid >> 3;      // ty: 0..15 (c octet)
    __shared__ float As[KC][132];   // [nn][c]  (transposed f)
    __shared__ float Bs[KC][68];    // [nn][k]
    const float* fr = f + (size_t)bi * CC * NN + (size_t)(c0 + tid) * NN;
    const float* ap = g_attn + (size_t)bi * NN * KK;

    u64 acc2[8][4];
#pragma unroll
    for (int i = 0; i < 8; i++)
#pragma unroll
        for (int j = 0; j < 4; j++) acc2[i][j] = 0ull;

    for (int n0 = nbeg; n0 < nbeg + NN / NSPLIT; n0 += KC) {
        // f transposed: thread tid owns column c = c0+tid, loads 16 n's (64B contig)
        float4 q0 = *(const float4*)&fr[n0];
        float4 q1 = *(const float4*)&fr[n0 + 4];
        float4 q2 = *(const float4*)&fr[n0 + 8];
        float4 q3 = *(const float4*)&fr[n0 + 12];
        As[0][tid] = q0.x;  As[1][tid] = q0.y;  As[2][tid] = q0.z;  As[3][tid] = q0.w;
        As[4][tid] = q1.x;  As[5][tid] = q1.y;  As[6][tid] = q1.z;  As[7][tid] = q1.w;
        As[8][tid] = q2.x;  As[9][tid] = q2.y;  As[10][tid] = q2.z; As[11][tid] = q2.w;
        As[12][tid] = q3.x; As[13][tid] = q3.y; As[14][tid] = q3.z; As[15][tid] = q3.w;
#pragma unroll
        for (int l = 0; l < 2; l++) {                 // attn: 16x64
            int idx = tid + l * 128;
            int r = idx >> 4, c4 = idx & 15;
            *(float4*)&Bs[r][c4 * 4] = *(const float4*)&ap[(size_t)(n0 + r) * KK + c4 * 4];
        }
        __syncthreads();
#pragma unroll
        for (int nn = 0; nn < KC; nn++) {
            float4 a0 = *(float4*)&As[nn][ty * 8];
            float4 a1 = *(float4*)&As[nn][ty * 8 + 4];
            float4 b0 = *(float4*)&Bs[nn][tx * 4];
            float4 b1 = *(float4*)&Bs[nn][tx * 4 + 32];
            u64 bp[4] = { pk2(b0.x, b0.y), pk2(b0.z, b0.w), pk2(b1.x, b1.y), pk2(b1.z, b1.w) };
            float av[8] = { a0.x, a0.y, a0.z, a0.w, a1.x, a1.y, a1.z, a1.w };
#pragma unroll
            for (int i = 0; i < 8; i++) {
                u64 ad = dup2(av[i]);
                fma2(acc2[i][0], ad, bp[0]);
                fma2(acc2[i][1], ad, bp[1]);
                fma2(acc2[i][2], ad, bp[2]);
                fma2(acc2[i][3], ad, bp[3]);
            }
        }
        __syncthreads();
    }

    const float* cs = g_colsum + bi * KK;
    float sc[8];
#pragma unroll
    for (int j = 0; j < 4; j++) sc[j]     = 1.f / (EPSF + cs[tx * 4 + j]);
#pragma unroll
    for (int j = 0; j < 4; j++) sc[4 + j] = 1.f / (EPSF + cs[32 + tx * 4 + j]);

    float* bo = g_bsplit + ((size_t)blockIdx.x * BB + bi) * CC * KK + (size_t)c0 * KK;
#pragma unroll
    for (int i = 0; i < 8; i++) {
        float2 e0 = up2(acc2[i][0]), e1 = up2(acc2[i][1]);
        float2 e2 = up2(acc2[i][2]), e3 = up2(acc2[i][3]);
        float* row = bo + (size_t)(ty * 8 + i) * KK;
        *(float4*)(row + tx * 4)      = make_float4(e0.x * sc[0], e0.y * sc[1], e1.x * sc[2], e1.y * sc[3]);
        *(float4*)(row + 32 + tx * 4) = make_float4(e2.x * sc[4], e2.y * sc[5], e3.x * sc[6], e3.y * sc[7]);
    }
}

// ---------------------------------------------------------------------------
// Sum the NSPLIT partial buffers (fully coalesced).
__global__ void k_reduce() {
    int i = blockIdx.x * blockDim.x + threadIdx.x;
    if (i >= BB * CC * KK) return;
    float s = 0.f;
#pragma unroll
    for (int sp = 0; sp < NSPLIT; sp++) s += g_bsplit[(size_t)sp * BB * CC * KK + i];
    g_bnew[i] = s;
}

// ---------------------------------------------------------------------------
// l2-normalize bnew over C -> g_b
__global__ void k_l2() {
    int bi = blockIdx.x >> 6, k = blockIdx.x & 63, t = threadIdx.x;
    __shared__ float red[128];
    const float* src = g_bnew + bi * CC * KK + k;
    float ss = 0.f;
    for (int c = t; c < CC; c += 128) { float v = src[c * KK]; ss += v * v; }
    red[t] = ss; __syncthreads();
    for (int s = 64; s > 0; s >>= 1) { if (t < s) red[t] += red[t + s]; __syncthreads(); }
    float inv = 1.f / (EPSF + sqrtf(red[0]));
    float* dst = g_b + bi * CC * KK + k;
    for (int c = t; c < CC; c += 128) dst[c * KK] = src[c * KK] * inv;
}

// ---------------------------------------------------------------------------
// Reconstruction: out[c,n] = sum_k b[c,k]*attn[n,k]
// 128 threads, tile 128c x 64n, reduction over K=64 in 4 chunks.
__global__ void __launch_bounds__(128) k_recon(float* __restrict__ out) {
    int bi = blockIdx.z, c0 = blockIdx.y * 128, n0 = blockIdx.x * 64;
    int tid = threadIdx.x, tx = tid & 7, ty = tid >> 3;      // ty: 0..15 (c octet)
    __shared__ float Bt[KC][132];   // [kk][c]
    __shared__ float At[KC][68];    // [kk][n]
    const float* bb = g_b + bi * CC * KK;
    const float* ap = g_attn + (size_t)bi * NN * KK;

    u64 acc2[8][4];
#pragma unroll
    for (int i = 0; i < 8; i++)
#pragma unroll
        for (int j = 0; j < 4; j++) acc2[i][j] = 0ull;

    for (int k0 = 0; k0 < KK; k0 += KC) {
        {   // Bt: b[c][k] -> Bt[k][c]; thread owns c = c0+tid, 16 k's (64B contig)
            const float* br = bb + (size_t)(c0 + tid) * KK + k0;
            float4 q0 = *(const float4*)&br[0];
            float4 q1 = *(const float4*)&br[4];
            float4 q2 = *(const float4*)&br[8];
            float4 q3 = *(const float4*)&br[12];
            Bt[0][tid] = q0.x;  Bt[1][tid] = q0.y;  Bt[2][tid] = q0.z;  Bt[3][tid] = q0.w;
            Bt[4][tid] = q1.x;  Bt[5][tid] = q1.y;  Bt[6][tid] = q1.z;  Bt[7][tid] = q1.w;
            Bt[8][tid] = q2.x;  Bt[9][tid] = q2.y;  Bt[10][tid] = q2.z; Bt[11][tid] = q2.w;
            Bt[12][tid] = q3.x; Bt[13][tid] = q3.y; Bt[14][tid] = q3.z; Bt[15][tid] = q3.w;
        }
        {   // At: attn[n][k] -> At[k][n]; pair of threads per n, 8 k's each (32B)
            int n = tid >> 1, kq = (tid & 1) * 8;
            const float* ar = ap + (size_t)(n0 + n) * KK + k0 + kq;
            float4 q0 = *(const float4*)&ar[0];
            float4 q1 = *(const float4*)&ar[4];
            At[kq + 0][n] = q0.x; At[kq + 1][n] = q0.y; At[kq + 2][n] = q0.z; At[kq + 3][n] = q0.w;
            At[kq + 4][n] = q1.x; At[kq + 5][n] = q1.y; At[kq + 6][n] = q1.z; At[kq + 7][n] = q1.w;
        }
        __syncthreads();
#pragma unroll
        for (int kk = 0; kk < KC; kk++) {
            float4 a0 = *(float4*)&Bt[kk][ty * 8];
            float4 a1 = *(float4*)&Bt[kk][ty * 8 + 4];
            float4 b0 = *(float4*)&At[kk][tx * 4];
            float4 b1 = *(float4*)&At[kk][tx * 4 + 32];
            u64 bp[4] = { pk2(b0.x, b0.y), pk2(b0.z, b0.w), pk2(b1.x, b1.y), pk2(b1.z, b1.w) };
            float av[8] = { a0.x, a0.y, a0.z, a0.w, a1.x, a1.y, a1.z, a1.w };
#pragma unroll
            for (int i = 0; i < 8; i++) {
                u64 ad = dup2(av[i]);
                fma2(acc2[i][0], ad, bp[0]);
                fma2(acc2[i][1], ad, bp[1]);
                fma2(acc2[i][2], ad, bp[2]);
                fma2(acc2[i][3], ad, bp[3]);
            }
        }
        __syncthreads();
    }

    float* op = out + ((size_t)bi * CC + c0) * NN + n0;
#pragma unroll
    for (int i = 0; i < 8; i++) {
        float2 e0 = up2(acc2[i][0]), e1 = up2(acc2[i][1]);
        float2 e2 = up2(acc2[i][2]), e3 = up2(acc2[i][3]);
        float* row = op + (size_t)(ty * 8 + i) * NN;
        *(float4*)(row + tx * 4)      = make_float4(e0.x, e0.y, e1.x, e1.y);
        *(float4*)(row + 32 + tx * 4) = make_float4(e2.x, e2.y, e3.x, e3.y);
    }
}

// ---------------------------------------------------------------------------
extern "C" void kernel_launch(void* const* d_in, const int* in_sizes, int n_in,
                              void* d_out, int out_size) {
    const float* feats = (const float*)d_in[0];   // [16,512,64,64]
    const float* bases = (const float*)d_in[1];   // [1,512,64]
    float* out = (float*)d_out;

    k_bases<<<KK, 128>>>(bases);
    for (int s = 0; s < 3; s++) {
        k_zero_cs<<<1, 1024>>>();
        k_gemm1<<<dim3(NN / 128, BB), 128>>>(feats);
        k_gemm2<<<dim3(NSPLIT, CC / 128, BB), 128>>>(feats);
        k_reduce<<<(BB * CC * KK + 255) / 256, 256>>>();
        k_l2<<<BB * KK, 128>>>();
    }
    k_recon<<<dim3(NN / 64, CC / 128, BB), 128>>>(out);
}

// round 7
// speedup vs baseline: 1.4908x; 1.4908x over previous
#include <cuda_runtime.h>
#include <cuda_bf16.h>
#include <stdint.h>
#include <math.h>

#define BB 16
#define CC 512
#define NN 4096
#define KK 64
#define NSPLIT 4
#define EPSF 1e-6f
typedef __nv_bfloat16 bf16;

// ---- scratch (allocation-free) ----
__device__ bf16 g_fnc_h[(size_t)BB*NN*CC], g_fnc_l[(size_t)BB*NN*CC];  // f [n][c] hi/lo
__device__ bf16 g_fcn_h[(size_t)BB*CC*NN], g_fcn_l[(size_t)BB*CC*NN];  // f [c][n] hi/lo
__device__ bf16 g_bkc_h[BB*KK*CC], g_bkc_l[BB*KK*CC];                  // bases [k][c]
__device__ bf16 g_bck_h[BB*CC*KK], g_bck_l[BB*CC*KK];                  // bases [c][k]
__device__ bf16 g_ank_h[(size_t)BB*NN*KK], g_ank_l[(size_t)BB*NN*KK];  // attn [n][k]
__device__ bf16 g_akn_h[(size_t)BB*KK*NN], g_akn_l[(size_t)BB*KK*NN];  // attn [k][n]
__device__ float g_bsplit[NSPLIT*BB*CC*KK];
__device__ float g_bnew[BB*CC*KK];
__device__ float g_colsum[BB*KK];

// dyn smem: A_HI 0..16K, A_LO 16K..32K, B_HI 32K..40K, B_LO 40K..48K  (= 49152 total)
// NOTE: zero static __shared__ in the GEMM kernels so total stays at the 48KB no-opt-in cap.
#define A_HI 0
#define A_LO 16384
#define B_HI 32768
#define B_LO 40960
#define SM_G 49152
extern __shared__ char dynsm[];

// ---- helpers ----
__device__ __forceinline__ uint32_t smem_u32(const void* p) {
    uint32_t a; asm("{.reg .u64 t; cvta.to.shared.u64 t, %1; cvt.u32.u64 %0, t;}" : "=r"(a) : "l"(p)); return a;
}
__device__ __forceinline__ uint32_t swz(uint32_t o) { return o ^ ((o >> 3) & 0x70); }
__device__ __forceinline__ void sts128(uint32_t a, uint4 v) {
    asm volatile("st.shared.v4.b32 [%0], {%1,%2,%3,%4};" :: "r"(a), "r"(v.x), "r"(v.y), "r"(v.z), "r"(v.w));
}
__device__ __forceinline__ uint32_t pbf2(float lo, float hi) {
    uint32_t r; asm("cvt.rn.bf16x2.f32 %0, %1, %2;" : "=r"(r) : "f"(hi), "f"(lo)); return r;
}
__device__ __forceinline__ void split8(const float* v, uint4& h, uint4& l) {
    uint32_t hp[4]; float lo[8];
#pragma unroll
    for (int p = 0; p < 4; p++) {
        hp[p] = pbf2(v[2*p], v[2*p+1]);
        lo[2*p]   = v[2*p]   - __uint_as_float(hp[p] << 16);
        lo[2*p+1] = v[2*p+1] - __uint_as_float(hp[p] & 0xffff0000u);
    }
    h = make_uint4(hp[0], hp[1], hp[2], hp[3]);
    l = make_uint4(pbf2(lo[0],lo[1]), pbf2(lo[2],lo[3]), pbf2(lo[4],lo[5]), pbf2(lo[6],lo[7]));
}
__device__ __forceinline__ void ldm4(uint32_t* r, uint32_t a) {
    asm volatile("ldmatrix.sync.aligned.m8n8.x4.shared.b16 {%0,%1,%2,%3}, [%4];"
        : "=r"(r[0]), "=r"(r[1]), "=r"(r[2]), "=r"(r[3]) : "r"(a));
}
__device__ __forceinline__ void mmab(float* d, const uint32_t* a, uint32_t b0, uint32_t b1) {
    asm volatile("mma.sync.aligned.m16n8k16.row.col.f32.bf16.bf16.f32 "
        "{%0,%1,%2,%3}, {%4,%5,%6,%7}, {%8,%9}, {%0,%1,%2,%3};"
        : "+f"(d[0]), "+f"(d[1]), "+f"(d[2]), "+f"(d[3])
        : "r"(a[0]), "r"(a[1]), "r"(a[2]), "r"(a[3]), "r"(b0), "r"(b1));
}
// stage NR rows of 64 bf16 (128B) into SW128 tile; 256 threads
template<int NR>
__device__ __forceinline__ void stage(uint32_t sbase, const bf16* src, size_t stride, int tid) {
    int g = tid & 7, r0 = tid >> 3;   // 0..31
#pragma unroll
    for (int m = 0; m < NR/32; m++) {
        int r = r0 + m*32;
        uint4 v = *(const uint4*)(src + (size_t)r*stride + g*8);
        sts128(sbase + swz((uint32_t)(r*128 + g*16)), v);
    }
}
// compute fragment ldmatrix offsets once (8 A + 8 B per thread)
__device__ __forceinline__ void mk_offsets(int tid, uint32_t* aoff, uint32_t* boff) {
    int lane = tid & 31, lm = lane >> 3, lr = lane & 7;
    int wm = (tid >> 6), wn = (tid >> 5) & 1;
#pragma unroll
    for (int f = 0; f < 2; f++)
#pragma unroll
        for (int ks = 0; ks < 4; ks++)
            aoff[f*4+ks] = swz((uint32_t)((wm*32 + f*16 + lr + (lm&1)*8)*128 + (ks*16 + (lm>>1)*8)*2));
#pragma unroll
    for (int p = 0; p < 2; p++)
#pragma unroll
        for (int ks = 0; ks < 4; ks++)
            boff[p*4+ks] = swz((uint32_t)((wn*32 + p*16 + (lm>>1)*8 + lr)*128 + (ks*16 + (lm&1)*8)*2));
}
// one 64-deep reduction chunk: 3 precision passes (hh, hl, lh)
__device__ __forceinline__ void gemm_chunk(float acc[2][4][4], uint32_t sb,
                                           const uint32_t* aoff, const uint32_t* boff) {
#pragma unroll
    for (int ks = 0; ks < 4; ks++) {
        uint32_t Ah[2][4], Al[2][4], Bh[2][4], Bl[2][4];
#pragma unroll
        for (int f = 0; f < 2; f++) {
            ldm4(Ah[f], sb + A_HI + aoff[f*4+ks]);
            ldm4(Al[f], sb + A_LO + aoff[f*4+ks]);
        }
#pragma unroll
        for (int p = 0; p < 2; p++) {
            ldm4(Bh[p], sb + B_HI + boff[p*4+ks]);
            ldm4(Bl[p], sb + B_LO + boff[p*4+ks]);
        }
#pragma unroll
        for (int f = 0; f < 2; f++)
#pragma unroll
            for (int o = 0; o < 4; o++) {
                mmab(acc[f][o], Ah[f], Bh[o>>1][(o&1)*2], Bh[o>>1][(o&1)*2+1]);
                mmab(acc[f][o], Ah[f], Bl[o>>1][(o&1)*2], Bl[o>>1][(o&1)*2+1]);
                mmab(acc[f][o], Al[f], Bh[o>>1][(o&1)*2], Bh[o>>1][(o&1)*2+1]);
            }
    }
}

// ---- prep: split f into bf16 hi/lo in both layouts ----
__global__ void k_pre(const float* __restrict__ f) {
    __shared__ unsigned short th[32][33], tl[32][33];
    int bi = blockIdx.z, c0 = blockIdx.y*32, n0 = blockIdx.x*32;
    int tx = threadIdx.x, ty = threadIdx.y;
#pragma unroll
    for (int i = 0; i < 4; i++) {
        int c = ty + i*8;
        size_t o = ((size_t)bi*CC + c0 + c)*NN + n0 + tx;
        float v = f[o];
        bf16 h = __float2bfloat16(v);
        bf16 l = __float2bfloat16(v - __bfloat162float(h));
        g_fcn_h[o] = h; g_fcn_l[o] = l;
        th[c][tx] = *(unsigned short*)&h; tl[c][tx] = *(unsigned short*)&l;
    }
    __syncthreads();
#pragma unroll
    for (int i = 0; i < 4; i++) {
        int n = ty + i*8;
        size_t o = ((size_t)bi*NN + n0 + n)*CC + c0 + tx;
        *(unsigned short*)&g_fnc_h[o] = th[tx][n];
        *(unsigned short*)&g_fnc_l[o] = tl[tx][n];
    }
}

__global__ void k_bases(const float* __restrict__ bases) {
    int k = blockIdx.x, t = threadIdx.x;
    __shared__ float red[128];
    float ss = 0.f;
    for (int c = t; c < CC; c += 128) { float v = bases[c*KK + k]; ss += v*v; }
    red[t] = ss; __syncthreads();
    for (int s = 64; s; s >>= 1) { if (t < s) red[t] += red[t+s]; __syncthreads(); }
    float inv = 1.f/(EPSF + sqrtf(red[0]));
    for (int c = t; c < CC; c += 128) {
        float v = bases[c*KK + k]*inv;
        bf16 h = __float2bfloat16(v);
        bf16 l = __float2bfloat16(v - __bfloat162float(h));
        for (int bi = 0; bi < BB; bi++) {
            size_t o = ((size_t)bi*KK + k)*CC + c;
            g_bkc_h[o] = h; g_bkc_l[o] = l;
        }
    }
}

__global__ void k_zero_cs() { if (threadIdx.x < BB*KK) g_colsum[threadIdx.x] = 0.f; }

__global__ void k_reduce() {
    int i = blockIdx.x*blockDim.x + threadIdx.x;
    if (i >= BB*CC*KK) return;
    float s = 0.f;
#pragma unroll
    for (int sp = 0; sp < NSPLIT; sp++) s += g_bsplit[(size_t)sp*BB*CC*KK + i];
    g_bnew[i] = s;
}

__global__ void k_l2() {
    int bi = blockIdx.x >> 6, k = blockIdx.x & 63, t = threadIdx.x;
    __shared__ float red[128];
    const float* src = g_bnew + bi*CC*KK + k;
    float ss = 0.f;
    for (int c = t; c < CC; c += 128) { float v = src[c*KK]; ss += v*v; }
    red[t] = ss; __syncthreads();
    for (int s = 64; s; s >>= 1) { if (t < s) red[t] += red[t+s]; __syncthreads(); }
    float inv = 1.f/(EPSF + sqrtf(red[0]));
    for (int c = t; c < CC; c += 128) {
        float v = src[c*KK]*inv;
        bf16 h = __float2bfloat16(v);
        bf16 l = __float2bfloat16(v - __bfloat162float(h));
        size_t okc = ((size_t)bi*KK + k)*CC + c, ock = ((size_t)bi*CC + c)*KK + k;
        g_bkc_h[okc] = h; g_bkc_l[okc] = l;
        g_bck_h[ock] = h; g_bck_l[ock] = l;
    }
}

// ---- GEMM1: logits[n,k] = fnc[n,:]·bkc[k,:]; softmax over k; emit attn + colsum ----
__global__ void __launch_bounds__(256) k_gemm1() {
    int bi = blockIdx.y, n0 = blockIdx.x*128;
    int tid = threadIdx.x;
    uint32_t sb = smem_u32(dynsm);
    uint32_t aoff[8], boff[8];
    mk_offsets(tid, aoff, boff);
    float acc[2][4][4];
#pragma unroll
    for (int f = 0; f < 2; f++)
#pragma unroll
        for (int o = 0; o < 4; o++)
#pragma unroll
            for (int q = 0; q < 4; q++) acc[f][o][q] = 0.f;

    const bf16 *fah = g_fnc_h + ((size_t)bi*NN + n0)*CC, *fal = g_fnc_l + ((size_t)bi*NN + n0)*CC;
    const bf16 *bah = g_bkc_h + (size_t)bi*KK*CC,        *bal = g_bkc_l + (size_t)bi*KK*CC;

    for (int ci = 0; ci < 8; ci++) {
        stage<128>(sb + A_HI, fah + ci*64, CC, tid);
        stage<128>(sb + A_LO, fal + ci*64, CC, tid);
        stage<64> (sb + B_HI, bah + ci*64, CC, tid);
        stage<64> (sb + B_LO, bal + ci*64, CC, tid);
        __syncthreads();
        gemm_chunk(acc, sb, aoff, boff);
        __syncthreads();
    }

    // accums -> smem tile [128][65] fp32 (reuses dynamic smem; 33280B < 48K)
    float* tile = (float*)dynsm;
    {
        int lane = tid & 31, g2 = lane >> 2, tg = lane & 3;
        int wm = tid >> 6, wn = (tid >> 5) & 1;
#pragma unroll
        for (int f = 0; f < 2; f++)
#pragma unroll
            for (int o = 0; o < 4; o++) {
                int r = wm*32 + f*16 + g2, cb = wn*32 + o*8 + tg*2;
                tile[r*65 + cb]       = acc[f][o][0];
                tile[r*65 + cb + 1]   = acc[f][o][1];
                tile[(r+8)*65 + cb]   = acc[f][o][2];
                tile[(r+8)*65 + cb+1] = acc[f][o][3];
            }
    }
    __syncthreads();

    if (tid < 128) {
        float v[64];
#pragma unroll
        for (int j = 0; j < 64; j++) v[j] = tile[tid*65 + j];
        float mx = v[0];
#pragma unroll
        for (int j = 1; j < 64; j++) mx = fmaxf(mx, v[j]);
        float s = 0.f;
#pragma unroll
        for (int j = 0; j < 64; j++) { float e = __expf(v[j] - mx); v[j] = e; s += e; }
        float inv = 1.f / s;
#pragma unroll
        for (int j = 0; j < 64; j++) { v[j] *= inv; tile[tid*65 + j] = v[j]; }
        size_t ro = ((size_t)bi*NN + n0 + tid)*KK;
#pragma unroll
        for (int g = 0; g < 8; g++) {
            uint4 h, l; split8(v + g*8, h, l);
            *(uint4*)(g_ank_h + ro + g*8) = h;
            *(uint4*)(g_ank_l + ro + g*8) = l;
        }
    }
    __syncthreads();
    if (tid < 64) {
        float cs = 0.f;
#pragma unroll 16
        for (int r = 0; r < 128; r++) cs += tile[r*65 + tid];
        atomicAdd(&g_colsum[bi*KK + tid], cs);
    }
    if (tid < 128) {
        int k = tid >> 1, nh = tid & 1;
        size_t ro = ((size_t)bi*KK + k)*NN + n0 + nh*64;
#pragma unroll
        for (int n8 = 0; n8 < 8; n8++) {
            float w[8];
#pragma unroll
            for (int j = 0; j < 8; j++) w[j] = tile[(nh*64 + n8*8 + j)*65 + k];
            uint4 h, l; split8(w, h, l);
            *(uint4*)(g_akn_h + ro + n8*8) = h;
            *(uint4*)(g_akn_l + ro + n8*8) = l;
        }
    }
}

// ---- GEMM2: bsplit[c,k] = (sum_{n in split} fcn[c,n]*akn[k,n]) * inv_colsum[k] ----
__global__ void __launch_bounds__(256) k_gemm2() {
    int bi = blockIdx.z, c0 = blockIdx.y*128, nb = blockIdx.x*(NN/NSPLIT);
    int tid = threadIdx.x;
    uint32_t sb = smem_u32(dynsm);
    uint32_t aoff[8], boff[8];
    mk_offsets(tid, aoff, boff);
    float acc[2][4][4];
#pragma unroll
    for (int f = 0; f < 2; f++)
#pragma unroll
        for (int o = 0; o < 4; o++)
#pragma unroll
            for (int q = 0; q < 4; q++) acc[f][o][q] = 0.f;

    const bf16 *fah = g_fcn_h + ((size_t)bi*CC + c0)*NN + nb, *fal = g_fcn_l + ((size_t)bi*CC + c0)*NN + nb;
    const bf16 *bah = g_akn_h + (size_t)bi*KK*NN + nb,        *bal = g_akn_l + (size_t)bi*KK*NN + nb;

    for (int ci = 0; ci < NN/NSPLIT/64; ci++) {
        stage<128>(sb + A_HI, fah + ci*64, NN, tid);
        stage<128>(sb + A_LO, fal + ci*64, NN, tid);
        stage<64> (sb + B_HI, bah + ci*64, NN, tid);
        stage<64> (sb + B_LO, bal + ci*64, NN, tid);
        __syncthreads();
        gemm_chunk(acc, sb, aoff, boff);
        __syncthreads();
    }

    // epilogue: read colsum directly from global (L2-resident, 8 values/thread)
    int lane = tid & 31, g2 = lane >> 2, tg = lane & 3;
    int wm = tid >> 6, wn = (tid >> 5) & 1;
    const float* cs = g_colsum + bi*KK;
    float* dst = g_bsplit + ((size_t)(blockIdx.x*BB + bi)*CC + c0)*KK;
#pragma unroll
    for (int f = 0; f < 2; f++)
#pragma unroll
        for (int o = 0; o < 4; o++) {
            int r = wm*32 + f*16 + g2, cb = wn*32 + o*8 + tg*2;
            float s0 = 1.f/(EPSF + cs[cb]), s1 = 1.f/(EPSF + cs[cb+1]);
            *(float2*)&dst[r*KK + cb]     = make_float2(acc[f][o][0]*s0, acc[f][o][1]*s1);
            *(float2*)&dst[(r+8)*KK + cb] = make_float2(acc[f][o][2]*s0, acc[f][o][3]*s1);
        }
}

// ---- RECON: out[c,n] = sum_k bck[c,k]*ank[n,k]; 128c x 64n, K=64 ----
__global__ void __launch_bounds__(256) k_recon(float* __restrict__ out) {
    int bi = blockIdx.z, c0 = blockIdx.y*128, n0 = blockIdx.x*64;
    int tid = threadIdx.x;
    uint32_t sb = smem_u32(dynsm);
    uint32_t aoff[8], boff[8];
    mk_offsets(tid, aoff, boff);
    float acc[2][4][4];
#pragma unroll
    for (int f = 0; f < 2; f++)
#pragma unroll
        for (int o = 0; o < 4; o++)
#pragma unroll
            for (int q = 0; q < 4; q++) acc[f][o][q] = 0.f;

    stage<128>(sb + A_HI, g_bck_h + ((size_t)bi*CC + c0)*KK, KK, tid);
    stage<128>(sb + A_LO, g_bck_l + ((size_t)bi*CC + c0)*KK, KK, tid);
    stage<64> (sb + B_HI, g_ank_h + ((size_t)bi*NN + n0)*KK, KK, tid);
    stage<64> (sb + B_LO, g_ank_l + ((size_t)bi*NN + n0)*KK, KK, tid);
    __syncthreads();
    gemm_chunk(acc, sb, aoff, boff);

    int lane = tid & 31, g2 = lane >> 2, tg = lane & 3;
    int wm = tid >> 6, wn = (tid >> 5) & 1;
    float* dst = out + ((size_t)bi*CC + c0)*NN + n0;
#pragma unroll
    for (int f = 0; f < 2; f++)
#pragma unroll
        for (int o = 0; o < 4; o++) {
            int r = wm*32 + f*16 + g2, cb = wn*32 + o*8 + tg*2;
            *(float2*)&dst[(size_t)r*NN + cb]     = make_float2(acc[f][o][0], acc[f][o][1]);
            *(float2*)&dst[(size_t)(r+8)*NN + cb] = make_float2(acc[f][o][2], acc[f][o][3]);
        }
}

// ---------------------------------------------------------------------------
extern "C" void kernel_launch(void* const* d_in, const int* in_sizes, int n_in,
                              void* d_out, int out_size) {
    const float* feats = (const float*)d_in[0];
    const float* bases = (const float*)d_in[1];
    float* out = (float*)d_out;

    k_pre<<<dim3(NN/32, CC/32, BB), dim3(32, 8)>>>(feats);
    k_bases<<<KK, 128>>>(bases);
    for (int s = 0; s < 3; s++) {
        k_zero_cs<<<1, 1024>>>();
        k_gemm1<<<dim3(NN/128, BB), 256, SM_G>>>();
        k_gemm2<<<dim3(NSPLIT, CC/128, BB), 256, SM_G>>>();
        k_reduce<<<(BB*CC*KK + 255)/256, 256>>>();
        k_l2<<<BB*KK, 128>>>();
    }
    k_recon<<<dim3(NN/64, CC/128, BB), 256, SM_G>>>(out);
}

// round 8
// speedup vs baseline: 1.6038x; 1.0758x over previous
#include <cuda_runtime.h>
#include <cuda_bf16.h>
#include <stdint.h>
#include <math.h>

#define BB 16
#define CC 512
#define NN 4096
#define KK 64
#define NSPLIT 4
#define EPSF 1e-6f
typedef __nv_bfloat16 bf16;

// ---- scratch (allocation-free) ----
__device__ bf16 g_fnc_h[(size_t)BB*NN*CC], g_fnc_l[(size_t)BB*NN*CC];  // f [n][c] hi/lo
__device__ bf16 g_fcn_h[(size_t)BB*CC*NN], g_fcn_l[(size_t)BB*CC*NN];  // f [c][n] hi/lo
__device__ bf16 g_bkc_h[BB*KK*CC], g_bkc_l[BB*KK*CC];                  // bases [k][c]
__device__ bf16 g_bck_h[BB*CC*KK], g_bck_l[BB*CC*KK];                  // bases [c][k]
__device__ bf16 g_ank_h[(size_t)BB*NN*KK], g_ank_l[(size_t)BB*NN*KK];  // attn [n][k]
__device__ bf16 g_akn_h[(size_t)BB*KK*NN], g_akn_l[(size_t)BB*KK*NN];  // attn [k][n]
__device__ float g_bsplit[NSPLIT*BB*CC*KK];
__device__ float g_bnew[BB*CC*KK];
__device__ float g_colsum[BB*KK];

// dyn smem: 2 pipeline buffers of 24KB (A_HI 8K | A_LO 8K | B_HI 4K | B_LO 4K) = 49152
#define BUF   24576
#define bA_HI 0
#define bA_LO 8192
#define bB_HI 16384
#define bB_LO 20480
#define SM_G  49152
extern __shared__ char dynsm[];

// ---- helpers ----
__device__ __forceinline__ uint32_t smem_u32(const void* p) {
    uint32_t a; asm("{.reg .u64 t; cvta.to.shared.u64 t, %1; cvt.u32.u64 %0, t;}" : "=r"(a) : "l"(p)); return a;
}
__device__ __forceinline__ uint32_t swz64(uint32_t o) { return o ^ ((o >> 3) & 0x30); }
__device__ __forceinline__ uint32_t pbf2(float lo, float hi) {
    uint32_t r; asm("cvt.rn.bf16x2.f32 %0, %1, %2;" : "=r"(r) : "f"(hi), "f"(lo)); return r;
}
__device__ __forceinline__ void split8(const float* v, uint4& h, uint4& l) {
    uint32_t hp[4]; float lo[8];
#pragma unroll
    for (int p = 0; p < 4; p++) {
        hp[p] = pbf2(v[2*p], v[2*p+1]);
        lo[2*p]   = v[2*p]   - __uint_as_float(hp[p] << 16);
        lo[2*p+1] = v[2*p+1] - __uint_as_float(hp[p] & 0xffff0000u);
    }
    h = make_uint4(hp[0], hp[1], hp[2], hp[3]);
    l = make_uint4(pbf2(lo[0],lo[1]), pbf2(lo[2],lo[3]), pbf2(lo[4],lo[5]), pbf2(lo[6],lo[7]));
}
__device__ __forceinline__ void ldm4(uint32_t* r, uint32_t a) {
    asm volatile("ldmatrix.sync.aligned.m8n8.x4.shared.b16 {%0,%1,%2,%3}, [%4];"
        : "=r"(r[0]), "=r"(r[1]), "=r"(r[2]), "=r"(r[3]) : "r"(a));
}
__device__ __forceinline__ void mmab(float* d, const uint32_t* a, uint32_t b0, uint32_t b1) {
    asm volatile("mma.sync.aligned.m16n8k16.row.col.f32.bf16.bf16.f32 "
        "{%0,%1,%2,%3}, {%4,%5,%6,%7}, {%8,%9}, {%0,%1,%2,%3};"
        : "+f"(d[0]), "+f"(d[1]), "+f"(d[2]), "+f"(d[3])
        : "r"(a[0]), "r"(a[1]), "r"(a[2]), "r"(a[3]), "r"(b0), "r"(b1));
}
__device__ __forceinline__ void cpa(uint32_t dst, const void* src) {
    asm volatile("cp.async.cg.shared.global [%0], [%1], 16;" :: "r"(dst), "l"(src));
}
__device__ __forceinline__ void cpa_commit() { asm volatile("cp.async.commit_group;" ::: "memory"); }
template<int N> __device__ __forceinline__ void cpa_wait() {
    asm volatile("cp.async.wait_group %0;" :: "n"(N) : "memory");
}
// stage A tile (128 rows x 32 bf16) / B tile (64 rows x 32 bf16), SW64 swizzled
__device__ __forceinline__ void stA(uint32_t b, const bf16* src, size_t stride, int tid) {
#pragma unroll
    for (int q = 0; q < 2; q++) {
        int idx = tid + q*256, r = idx >> 2, c = idx & 3;
        cpa(b + swz64((uint32_t)(r*64 + c*16)), src + (size_t)r*stride + c*8);
    }
}
__device__ __forceinline__ void stB(uint32_t b, const bf16* src, size_t stride, int tid) {
    int r = tid >> 2, c = tid & 3;
    cpa(b + swz64((uint32_t)(r*64 + c*16)), src + (size_t)r*stride + c*8);
}
__device__ __forceinline__ void issue(uint32_t sb, int buf, const bf16* ah, const bf16* al,
                                      const bf16* bh, const bf16* bl, size_t sA, size_t sB, int tid) {
    uint32_t bb = sb + buf*BUF;
    stA(bb + bA_HI, ah, sA, tid);
    stA(bb + bA_LO, al, sA, tid);
    stB(bb + bB_HI, bh, sB, tid);
    stB(bb + bB_LO, bl, sB, tid);
    cpa_commit();
}
// ldmatrix offsets for K-chunk=32 tiles (4 A + 4 B per thread)
__device__ __forceinline__ void mk_off32(int tid, uint32_t* aoff, uint32_t* boff) {
    int lane = tid & 31, lm = lane >> 3, lr = lane & 7;
    int wm = tid >> 6, wn = (tid >> 5) & 1;
#pragma unroll
    for (int f = 0; f < 2; f++)
#pragma unroll
        for (int ks = 0; ks < 2; ks++)
            aoff[f*2+ks] = swz64((uint32_t)((wm*32 + f*16 + lr + (lm&1)*8)*64 + (ks*16 + (lm>>1)*8)*2));
#pragma unroll
    for (int p = 0; p < 2; p++)
#pragma unroll
        for (int ks = 0; ks < 2; ks++)
            boff[p*2+ks] = swz64((uint32_t)((wn*32 + p*16 + (lm>>1)*8 + lr)*64 + (ks*16 + (lm&1)*8)*2));
}
// one 32-deep chunk: 3 precision passes (hh, hl, lh)
__device__ __forceinline__ void gemm_chunk32(float acc[2][4][4], uint32_t bb,
                                             const uint32_t* aoff, const uint32_t* boff) {
#pragma unroll
    for (int ks = 0; ks < 2; ks++) {
        uint32_t Ah[2][4], Al[2][4], Bh[2][4], Bl[2][4];
#pragma unroll
        for (int f = 0; f < 2; f++) {
            ldm4(Ah[f], bb + bA_HI + aoff[f*2+ks]);
            ldm4(Al[f], bb + bA_LO + aoff[f*2+ks]);
        }
#pragma unroll
        for (int p = 0; p < 2; p++) {
            ldm4(Bh[p], bb + bB_HI + boff[p*2+ks]);
            ldm4(Bl[p], bb + bB_LO + boff[p*2+ks]);
        }
#pragma unroll
        for (int f = 0; f < 2; f++)
#pragma unroll
            for (int o = 0; o < 4; o++) {
                mmab(acc[f][o], Ah[f], Bh[o>>1][(o&1)*2], Bh[o>>1][(o&1)*2+1]);
                mmab(acc[f][o], Ah[f], Bl[o>>1][(o&1)*2], Bl[o>>1][(o&1)*2+1]);
                mmab(acc[f][o], Al[f], Bh[o>>1][(o&1)*2], Bh[o>>1][(o&1)*2+1]);
            }
    }
}

// ---- prep: split f into bf16 hi/lo in both layouts ----
__global__ void k_pre(const float* __restrict__ f) {
    __shared__ unsigned short th[32][33], tl[32][33];
    int bi = blockIdx.z, c0 = blockIdx.y*32, n0 = blockIdx.x*32;
    int tx = threadIdx.x, ty = threadIdx.y;
#pragma unroll
    for (int i = 0; i < 4; i++) {
        int c = ty + i*8;
        size_t o = ((size_t)bi*CC + c0 + c)*NN + n0 + tx;
        float v = f[o];
        bf16 h = __float2bfloat16(v);
        bf16 l = __float2bfloat16(v - __bfloat162float(h));
        g_fcn_h[o] = h; g_fcn_l[o] = l;
        th[c][tx] = *(unsigned short*)&h; tl[c][tx] = *(unsigned short*)&l;
    }
    __syncthreads();
#pragma unroll
    for (int i = 0; i < 4; i++) {
        int n = ty + i*8;
        size_t o = ((size_t)bi*NN + n0 + n)*CC + c0 + tx;
        *(unsigned short*)&g_fnc_h[o] = th[tx][n];
        *(unsigned short*)&g_fnc_l[o] = tl[tx][n];
    }
}

__global__ void k_bases(const float* __restrict__ bases) {
    int k = blockIdx.x, t = threadIdx.x;
    __shared__ float red[128];
    float ss = 0.f;
    for (int c = t; c < CC; c += 128) { float v = bases[c*KK + k]; ss += v*v; }
    red[t] = ss; __syncthreads();
    for (int s = 64; s; s >>= 1) { if (t < s) red[t] += red[t+s]; __syncthreads(); }
    float inv = 1.f/(EPSF + sqrtf(red[0]));
    for (int c = t; c < CC; c += 128) {
        float v = bases[c*KK + k]*inv;
        bf16 h = __float2bfloat16(v);
        bf16 l = __float2bfloat16(v - __bfloat162float(h));
        for (int bi = 0; bi < BB; bi++) {
            size_t o = ((size_t)bi*KK + k)*CC + c;
            g_bkc_h[o] = h; g_bkc_l[o] = l;
        }
    }
}

__global__ void k_zero_cs() { if (threadIdx.x < BB*KK) g_colsum[threadIdx.x] = 0.f; }

__global__ void k_reduce() {
    int i = blockIdx.x*blockDim.x + threadIdx.x;
    if (i >= BB*CC*KK) return;
    float s = 0.f;
#pragma unroll
    for (int sp = 0; sp < NSPLIT; sp++) s += g_bsplit[(size_t)sp*BB*CC*KK + i];
    g_bnew[i] = s;
}

// ---- l2 normalize (coalesced), emit bkc+bck hi/lo, and zero colsum for next stage ----
__global__ void __launch_bounds__(256) k_l2() {
    int bi = blockIdx.x, t = threadIdx.x;
    __shared__ float part[4][64];
    __shared__ float inv[64];
    __shared__ unsigned short tih[64][72], til[64][72];
    int kq = t & 63, cg = t >> 6;
    const float* src = g_bnew + bi*CC*KK;
    float ss = 0.f;
    for (int c = cg; c < CC; c += 4) { float v = src[c*KK + kq]; ss += v*v; }
    part[cg][kq] = ss;
    __syncthreads();
    if (t < 64) inv[t] = 1.f/(EPSF + sqrtf(part[0][t]+part[1][t]+part[2][t]+part[3][t]));
    __syncthreads();
    for (int c0 = 0; c0 < CC; c0 += 64) {
#pragma unroll
        for (int i = 0; i < 16; i++) {
            int c = c0 + cg*16 + i;
            float v = src[c*KK + kq] * inv[kq];
            bf16 h = __float2bfloat16(v);
            bf16 l = __float2bfloat16(v - __bfloat162float(h));
            size_t o = ((size_t)bi*CC + c)*KK + kq;
            g_bck_h[o] = h; g_bck_l[o] = l;
            tih[c - c0][kq] = *(unsigned short*)&h;
            til[c - c0][kq] = *(unsigned short*)&l;
        }
        __syncthreads();
        int kr = t >> 2, cs = (t & 3) * 16;
        unsigned short wh[16], wl[16];
#pragma unroll
        for (int i = 0; i < 16; i++) { wh[i] = tih[cs+i][kr]; wl[i] = til[cs+i][kr]; }
        size_t ro = ((size_t)bi*KK + kr)*CC + c0 + cs;
#pragma unroll
        for (int q = 0; q < 2; q++) {
            *(uint4*)(g_bkc_h + ro + q*8) = *(uint4*)(wh + q*8);
            *(uint4*)(g_bkc_l + ro + q*8) = *(uint4*)(wl + q*8);
        }
        __syncthreads();
    }
    if (t < 64) g_colsum[bi*KK + t] = 0.f;
}

// ---- GEMM1: logits[n,k] = fnc[n,:]·bkc[k,:]; softmax over k; emit attn + colsum ----
__global__ void __launch_bounds__(256) k_gemm1() {
    int bi = blockIdx.y, n0 = blockIdx.x*128;
    int tid = threadIdx.x;
    uint32_t sb = smem_u32(dynsm);
    uint32_t aoff[4], boff[4];
    mk_off32(tid, aoff, boff);
    float acc[2][4][4];
#pragma unroll
    for (int f = 0; f < 2; f++)
#pragma unroll
        for (int o = 0; o < 4; o++)
#pragma unroll
            for (int q = 0; q < 4; q++) acc[f][o][q] = 0.f;

    const bf16 *fah = g_fnc_h + ((size_t)bi*NN + n0)*CC, *fal = g_fnc_l + ((size_t)bi*NN + n0)*CC;
    const bf16 *bah = g_bkc_h + (size_t)bi*KK*CC,        *bal = g_bkc_l + (size_t)bi*KK*CC;

    issue(sb, 0, fah, fal, bah, bal, CC, CC, tid);
    for (int ci = 0; ci < 16; ci++) {
        int nx = ci+1 < 16 ? ci+1 : 15;
        issue(sb, (ci+1)&1, fah + nx*32, fal + nx*32, bah + nx*32, bal + nx*32, CC, CC, tid);
        cpa_wait<1>();
        __syncthreads();
        gemm_chunk32(acc, sb + (ci&1)*BUF, aoff, boff);
        __syncthreads();
    }
    cpa_wait<0>();
    __syncthreads();

    // accums -> smem tile [128][65] fp32 (reuses dynamic smem)
    float* tile = (float*)dynsm;
    {
        int lane = tid & 31, g2 = lane >> 2, tg = lane & 3;
        int wm = tid >> 6, wn = (tid >> 5) & 1;
#pragma unroll
        for (int f = 0; f < 2; f++)
#pragma unroll
            for (int o = 0; o < 4; o++) {
                int r = wm*32 + f*16 + g2, cb = wn*32 + o*8 + tg*2;
                tile[r*65 + cb]       = acc[f][o][0];
                tile[r*65 + cb + 1]   = acc[f][o][1];
                tile[(r+8)*65 + cb]   = acc[f][o][2];
                tile[(r+8)*65 + cb+1] = acc[f][o][3];
            }
    }
    __syncthreads();

    if (tid < 128) {
        float v[64];
#pragma unroll
        for (int j = 0; j < 64; j++) v[j] = tile[tid*65 + j];
        float mx = v[0];
#pragma unroll
        for (int j = 1; j < 64; j++) mx = fmaxf(mx, v[j]);
        float s = 0.f;
#pragma unroll
        for (int j = 0; j < 64; j++) { float e = __expf(v[j] - mx); v[j] = e; s += e; }
        float inv = 1.f / s;
#pragma unroll
        for (int j = 0; j < 64; j++) { v[j] *= inv; tile[tid*65 + j] = v[j]; }
        size_t ro = ((size_t)bi*NN + n0 + tid)*KK;
#pragma unroll
        for (int g = 0; g < 8; g++) {
            uint4 h, l; split8(v + g*8, h, l);
            *(uint4*)(g_ank_h + ro + g*8) = h;
            *(uint4*)(g_ank_l + ro + g*8) = l;
        }
    }
    __syncthreads();
    if (tid < 64) {
        float cs = 0.f;
#pragma unroll 16
        for (int r = 0; r < 128; r++) cs += tile[r*65 + tid];
        atomicAdd(&g_colsum[bi*KK + tid], cs);
    }
    if (tid < 128) {
        int k = tid >> 1, nh = tid & 1;
        size_t ro = ((size_t)bi*KK + k)*NN + n0 + nh*64;
#pragma unroll
        for (int n8 = 0; n8 < 8; n8++) {
            float w[8];
#pragma unroll
            for (int j = 0; j < 8; j++) w[j] = tile[(nh*64 + n8*8 + j)*65 + k];
            uint4 h, l; split8(w, h, l);
            *(uint4*)(g_akn_h + ro + n8*8) = h;
            *(uint4*)(g_akn_l + ro + n8*8) = l;
        }
    }
}

// ---- GEMM2: bsplit[c,k] = (sum_{n in split} fcn[c,n]*akn[k,n]) * inv_colsum[k] ----
__global__ void __launch_bounds__(256) k_gemm2() {
    int bi = blockIdx.z, c0 = blockIdx.y*128, nb = blockIdx.x*(NN/NSPLIT);
    int tid = threadIdx.x;
    uint32_t sb = smem_u32(dynsm);
    uint32_t aoff[4], boff[4];
    mk_off32(tid, aoff, boff);
    float acc[2][4][4];
#pragma unroll
    for (int f = 0; f < 2; f++)
#pragma unroll
        for (int o = 0; o < 4; o++)
#pragma unroll
            for (int q = 0; q < 4; q++) acc[f][o][q] = 0.f;

    const bf16 *fah = g_fcn_h + ((size_t)bi*CC + c0)*NN + nb, *fal = g_fcn_l + ((size_t)bi*CC + c0)*NN + nb;
    const bf16 *bah = g_akn_h + (size_t)bi*KK*NN + nb,        *bal = g_akn_l + (size_t)bi*KK*NN + nb;

    const int NCH = (NN/NSPLIT)/32;
    issue(sb, 0, fah, fal, bah, bal, NN, NN, tid);
    for (int ci = 0; ci < NCH; ci++) {
        int nx = ci+1 < NCH ? ci+1 : NCH-1;
        issue(sb, (ci+1)&1, fah + nx*32, fal + nx*32, bah + nx*32, bal + nx*32, NN, NN, tid);
        cpa_wait<1>();
        __syncthreads();
        gemm_chunk32(acc, sb + (ci&1)*BUF, aoff, boff);
        __syncthreads();
    }
    cpa_wait<0>();

    int lane = tid & 31, g2 = lane >> 2, tg = lane & 3;
    int wm = tid >> 6, wn = (tid >> 5) & 1;
    const float* cs = g_colsum + bi*KK;
    float* dst = g_bsplit + ((size_t)(blockIdx.x*BB + bi)*CC + c0)*KK;
#pragma unroll
    for (int f = 0; f < 2; f++)
#pragma unroll
        for (int o = 0; o < 4; o++) {
            int r = wm*32 + f*16 + g2, cb = wn*32 + o*8 + tg*2;
            float s0 = 1.f/(EPSF + cs[cb]), s1 = 1.f/(EPSF + cs[cb+1]);
            *(float2*)&dst[r*KK + cb]     = make_float2(acc[f][o][0]*s0, acc[f][o][1]*s1);
            *(float2*)&dst[(r+8)*KK + cb] = make_float2(acc[f][o][2]*s0, acc[f][o][3]*s1);
        }
}

// ---- RECON: out[c,n] = sum_k bck[c,k]*ank[n,k]; 128c x 64n, K=64 (2 chunks) ----
__global__ void __launch_bounds__(256) k_recon(float* __restrict__ out) {
    int bi = blockIdx.z, c0 = blockIdx.y*128, n0 = blockIdx.x*64;
    int tid = threadIdx.x;
    uint32_t sb = smem_u32(dynsm);
    uint32_t aoff[4], boff[4];
    mk_off32(tid, aoff, boff);
    float acc[2][4][4];
#pragma unroll
    for (int f = 0; f < 2; f++)
#pragma unroll
        for (int o = 0; o < 4; o++)
#pragma unroll
            for (int q = 0; q < 4; q++) acc[f][o][q] = 0.f;

    const bf16 *fah = g_bck_h + ((size_t)bi*CC + c0)*KK, *fal = g_bck_l + ((size_t)bi*CC + c0)*KK;
    const bf16 *bah = g_ank_h + ((size_t)bi*NN + n0)*KK, *bal = g_ank_l + ((size_t)bi*NN + n0)*KK;

    issue(sb, 0, fah, fal, bah, bal, KK, KK, tid);
    for (int ci = 0; ci < 2; ci++) {
        int nx = ci+1 < 2 ? ci+1 : 1;
        issue(sb, (ci+1)&1, fah + nx*32, fal + nx*32, bah + nx*32, bal + nx*32, KK, KK, tid);
        cpa_wait<1>();
        __syncthreads();
        gemm_chunk32(acc, sb + (ci&1)*BUF, aoff, boff);
        __syncthreads();
    }
    cpa_wait<0>();

    int lane = tid & 31, g2 = lane >> 2, tg = lane & 3;
    int wm = tid >> 6, wn = (tid >> 5) & 1;
    float* dst = out + ((size_t)bi*CC + c0)*NN + n0;
#pragma unroll
    for (int f = 0; f < 2; f++)
#pragma unroll
        for (int o = 0; o < 4; o++) {
            int r = wm*32 + f*16 + g2, cb = wn*32 + o*8 + tg*2;
            *(float2*)&dst[(size_t)r*NN + cb]     = make_float2(acc[f][o][0], acc[f][o][1]);
            *(float2*)&dst[(size_t)(r+8)*NN + cb] = make_float2(acc[f][o][2], acc[f][o][3]);
        }
}

// ---------------------------------------------------------------------------
extern "C" void kernel_launch(void* const* d_in, const int* in_sizes, int n_in,
                              void* d_out, int out_size) {
    const float* feats = (const float*)d_in[0];
    const float* bases = (const float*)d_in[1];
    float* out = (float*)d_out;

    k_pre<<<dim3(NN/32, CC/32, BB), dim3(32, 8)>>>(feats);
    k_bases<<<KK, 128>>>(bases);
    k_zero_cs<<<1, 1024>>>();
    for (int s = 0; s < 3; s++) {
        k_gemm1<<<dim3(NN/128, BB), 256, SM_G>>>();
        k_gemm2<<<dim3(NSPLIT, CC/128, BB), 256, SM_G>>>();
        k_reduce<<<(BB*CC*KK + 255)/256, 256>>>();
        k_l2<<<BB, 256>>>();
    }
    k_recon<<<dim3(NN/64, CC/128, BB), 256, SM_G>>>(out);
}